// round 11
// baseline (speedup 1.0000x reference)
#include <cuda_runtime.h>
#include <cstdint>
#include <cstddef>

// Problem constants
#define T_DIM 1024
#define M_DIM 128
#define A_DIM 64
#define D_DIM 128
#define NTHREADS 256

// ---------------- packed weight scratch (filled once by pack_weights) ----------------
// B-operand packed layout: entry (nt, ksp, slot) holds float4
//   e0 = B[16*ksp + q    ][8*nt + g]
//   e1 = B[16*ksp + q + 4][8*nt + g]
//   e2 = B[16*ksp + q + 8][8*nt + g]
//   e3 = B[16*ksp + q +12][8*nt + g]
// for consumer lane (g,q) stored at slot = g*4 + ((q + (g>>1)) & 3).
__device__ float g_W1p[16 * 4 * 32 * 4];   // W1: K=64  -> KSP=4   (8192 floats)
__device__ float g_W2p[16 * 8 * 32 * 4];   // W2: K=128 -> KSP=8   (16384 floats)

// ---------------- helpers ----------------
__device__ __forceinline__ unsigned f2tf32(float x) {
    unsigned u;
    asm("cvt.rna.tf32.f32 %0, %1;" : "=r"(u) : "f"(x));
    return u;
}
__device__ __forceinline__ float tf32f(float x) { return __uint_as_float(f2tf32(x)); }

// lane-slot permutation within a 32-lane packed group (bank spreading)
__device__ __forceinline__ int slot_of(int g, int q) { return g * 4 + ((q + (g >> 1)) & 3); }
__device__ __forceinline__ void inv_slot(int j, int& g, int& q) {
    g = j >> 2;
    q = ((j & 3) + 4 - ((g >> 1) & 3)) & 3;
}

__device__ __forceinline__ void mma_tf32(float c[4],
                                         unsigned a0, unsigned a1, unsigned a2, unsigned a3,
                                         unsigned b0, unsigned b1) {
    asm volatile(
        "mma.sync.aligned.m16n8k8.row.col.f32.tf32.tf32.f32 "
        "{%0,%1,%2,%3}, {%4,%5,%6,%7}, {%8,%9}, {%0,%1,%2,%3};"
        : "+f"(c[0]), "+f"(c[1]), "+f"(c[2]), "+f"(c[3])
        : "r"(a0), "r"(a1), "r"(a2), "r"(a3), "r"(b0), "r"(b1));
}

// ---------------- setup kernel: pack W1/W2 into fragment layout --------------
__global__ void pack_weights(const float* __restrict__ W1, const float* __restrict__ W2) {
    const int idx = blockIdx.x * 256 + threadIdx.x;   // 6144 total
    if (idx < 2048) {                                  // W1p: nt(16) x ksp(4) x slot(32)
        const int js = idx & 31, ksp = (idx >> 5) & 3, nt = idx >> 7;
        int g, q; inv_slot(js, g, q);
        const int n = nt * 8 + g, k0 = ksp * 16 + q;
        float4 v;
        v.x = tf32f(W1[(k0     ) * D_DIM + n]);
        v.y = tf32f(W1[(k0 +  4) * D_DIM + n]);
        v.z = tf32f(W1[(k0 +  8) * D_DIM + n]);
        v.w = tf32f(W1[(k0 + 12) * D_DIM + n]);
        *reinterpret_cast<float4*>(&g_W1p[idx * 4]) = v;
    } else {                                           // W2p: nt(16) x ksp(8) x slot(32)
        const int i2 = idx - 2048;
        const int js = i2 & 31, ksp = (i2 >> 5) & 7, nt = i2 >> 8;
        int g, q; inv_slot(js, g, q);
        const int n = nt * 8 + g, k0 = ksp * 16 + q;
        float4 v;
        v.x = tf32f(W2[(k0     ) * M_DIM + n]);
        v.y = tf32f(W2[(k0 +  4) * M_DIM + n]);
        v.z = tf32f(W2[(k0 +  8) * M_DIM + n]);
        v.w = tf32f(W2[(k0 + 12) * M_DIM + n]);
        *reinterpret_cast<float4*>(&g_W2p[i2 * 4]) = v;
    }
}

// ---------------- generic packed-fragment GEMM ----------------
// A packed: entry (rg, ks, slot) float4 = {A[16rg+g][8ks+q], A[16rg+g+8][8ks+q],
//                                          A[16rg+g][8ks+q+4], A[16rg+g+8][8ks+q+4]}
// B packed: entry (nt, ksp, slot) as documented above. KS = 2*KSP.
// Warp covers rows [16*rgbase, 16*rgbase+64) and col tiles [ntbase, ntbase+NTL).
template<int KSP, int NTL>
__device__ __forceinline__ void gemm_frag(const float* __restrict__ PA,
                                          const float* __restrict__ PB,
                                          int rgbase, int ntbase, int slotl,
                                          float acc[4][8][4]) {
    #pragma unroll
    for (int ksp = 0; ksp < KSP; ksp++) {
        float4 aE[4], aO[4];
        #pragma unroll
        for (int rgl = 0; rgl < 4; rgl++) {
            const int rg = rgbase + rgl;
            aE[rgl] = *reinterpret_cast<const float4*>(
                &PA[((rg * (2 * KSP) + 2 * ksp    ) * 32 + slotl) * 4]);
            aO[rgl] = *reinterpret_cast<const float4*>(
                &PA[((rg * (2 * KSP) + 2 * ksp + 1) * 32 + slotl) * 4]);
        }
        #pragma unroll
        for (int ntl = 0; ntl < NTL; ntl++) {
            const float4 b = *reinterpret_cast<const float4*>(
                &PB[(((ntbase + ntl) * KSP + ksp) * 32 + slotl) * 4]);
            #pragma unroll
            for (int rgl = 0; rgl < 4; rgl++) {
                mma_tf32(acc[rgl][ntl],
                         __float_as_uint(aE[rgl].x), __float_as_uint(aE[rgl].y),
                         __float_as_uint(aE[rgl].z), __float_as_uint(aE[rgl].w),
                         __float_as_uint(b.x), __float_as_uint(b.y));
                mma_tf32(acc[rgl][ntl],
                         __float_as_uint(aO[rgl].x), __float_as_uint(aO[rgl].y),
                         __float_as_uint(aO[rgl].z), __float_as_uint(aO[rgl].w),
                         __float_as_uint(b.z), __float_as_uint(b.w));
            }
        }
    }
}

__device__ __forceinline__ void zero_acc(float acc[4][8][4]) {
    #pragma unroll
    for (int a = 0; a < 4; a++)
        #pragma unroll
        for (int n = 0; n < 8; n++)
            #pragma unroll
            for (int r = 0; r < 4; r++) acc[a][n][r] = 0.0f;
}

// ---------------- SMEM layout (float offsets) ----------------
// R1 [0,16384):      X2 (packed A, 256 rows, KS=8)  UNION  Main(t) (packed A, 128 rows, KS=16)
// R2 [16384,49152):  H2 (packed A, 256 rows, KS=16) UNION  S2 (2 x packed-B, 16384 each)
// biases [49152,49408)
#define R1F    0
#define R2F    16384
#define B1O    49152
#define B2O    49280
#define SMEM_FLOATS 49408
#define SMEM_BYTES  (SMEM_FLOATS * 4)   // 197632

__global__ __launch_bounds__(NTHREADS, 1)
void slam_dual_kernel(const float* __restrict__ x_main_last,
                      const float* __restrict__ x_aux,
                      const float* __restrict__ b1,
                      const float* __restrict__ b2,
                      float* __restrict__ out) {
    extern __shared__ float sm[];
    const int t0   = blockIdx.x * 2;            // this CTA owns t0, t0+1
    const int tid  = threadIdx.x;
    const int warp = tid >> 5;
    const int lane = tid & 31;
    const int g    = lane >> 2;
    const int q    = lane & 3;
    // wide-phase decomposition (G1/G2): 4 row-groups x 2 col-groups of 64x64 tiles
    const int R    = warp >> 1;    // 0..3: rows 64R of the stacked 256
    const int C    = warp & 1;     // 0..1: cols 64C
    // G3 decomposition: 2 row-groups x 4 col-groups of 64x32 tiles
    const int rg2  = warp >> 2;    // 0..1
    const int cg   = warp & 3;     // 0..3
    const int slotl = slot_of(g, q);

    // ---------- Phase 0: stage X2 (both t's, packed-A, 256 rows KS=8), biases ----------
    {
        #pragma unroll
        for (int it = 0; it < 16; it++) {
            const int idx = tid + it * NTHREADS;            // 4096 entries
            const int js = idx & 31, ks = (idx >> 5) & 7, rg = idx >> 8;  // rg 0..15
            int gg, qq; inv_slot(js, gg, qq);
            const int tloc = rg >> 3;
            const int r0 = (rg & 7) * 16 + gg, c0 = ks * 8 + qq;
            const float* xp = x_aux + (size_t)(t0 + tloc) * A_DIM;
            const size_t rs = (size_t)(T_DIM * A_DIM);
            float4 v;
            v.x = tf32f(xp[(size_t)(r0    ) * rs + c0    ]);
            v.y = tf32f(xp[(size_t)(r0 + 8) * rs + c0    ]);
            v.z = tf32f(xp[(size_t)(r0    ) * rs + c0 + 4]);
            v.w = tf32f(xp[(size_t)(r0 + 8) * rs + c0 + 4]);
            *reinterpret_cast<float4*>(&sm[R1F + idx * 4]) = v;
        }
        if (tid < 128) {
            sm[B1O + tid] = b1[tid];
            sm[B2O + tid] = b2[tid];
        }
    }
    __syncthreads();

    float acc[4][8][4];
    const int hi  = (q >= 2) ? 2 : 0;
    const int qc0 = (2 * q) & 3;

    // ---------- G1 (stacked 256x64x128): H2 = relu([X(t0);X(t1)] @ W1 + b1) ----------
    zero_acc(acc);
    gemm_frag<4, 8>(&sm[R1F], g_W1p, 4 * R, 8 * C, slotl, acc);

    // epilogue1 -> H2 (packed-A, 256 rows, KS=16) in R2
    #pragma unroll
    for (int rgl = 0; rgl < 4; rgl++) {
        const int rg = 4 * R + rgl;                  // 0..15
        #pragma unroll
        for (int ntl = 0; ntl < 8; ntl++) {
            const int ks = 8 * C + ntl;              // 0..15
            const int d0 = 64 * C + 8 * ntl + 2 * q;
            const float bb0 = sm[B1O + d0], bb1 = sm[B1O + d0 + 1];
            const int base = R2F + (rg * 16 + ks) * 128;
            const int s0 = slot_of(g, qc0), s1 = slot_of(g, qc0 + 1);
            float2 w0, w1;
            w0.x = tf32f(fmaxf(acc[rgl][ntl][0] + bb0, 0.0f));
            w0.y = tf32f(fmaxf(acc[rgl][ntl][2] + bb0, 0.0f));
            w1.x = tf32f(fmaxf(acc[rgl][ntl][1] + bb1, 0.0f));
            w1.y = tf32f(fmaxf(acc[rgl][ntl][3] + bb1, 0.0f));
            *reinterpret_cast<float2*>(&sm[base + s0 * 4 + hi]) = w0;
            *reinterpret_cast<float2*>(&sm[base + s1 * 4 + hi]) = w1;
        }
    }
    __syncthreads();   // X2 reads + H2 writes complete

    // ---------- stage Main(t0) -> R1 (X2 dead), then G2 under the LDG shadow ----------
    {
        const float* mp = x_main_last + (size_t)t0 * (M_DIM * M_DIM);
        #pragma unroll
        for (int it = 0; it < 16; it++) {
            const int idx = tid + it * NTHREADS;            // 4096 entries
            const int js = idx & 31, ks = (idx >> 5) & 15, rg = idx >> 9;  // rg 0..7
            int gg, qq; inv_slot(js, gg, qq);
            const int r0 = rg * 16 + gg, c0 = ks * 8 + qq;
            float4 v;
            v.x = tf32f(mp[(r0    ) * M_DIM + c0    ]);
            v.y = tf32f(mp[(r0 + 8) * M_DIM + c0    ]);
            v.z = tf32f(mp[(r0    ) * M_DIM + c0 + 4]);
            v.w = tf32f(mp[(r0 + 8) * M_DIM + c0 + 4]);
            *reinterpret_cast<float4*>(&sm[R1F + idx * 4]) = v;
        }
    }

    // ---------- G2 (stacked 256x128x128): S2 = H2 @ W2 + b2 ----------
    zero_acc(acc);
    gemm_frag<8, 8>(&sm[R2F], g_W2p, 4 * R, 8 * C, slotl, acc);
    __syncthreads();   // H2 reads + Main(t0) STS complete

    // epilogue2 -> S2 (two packed-B blocks in R2; k-dim = j = local GEMM2 output row)
    {
        const int tloc = R >> 1;                     // which t this warp's rows belong to
        const int Rl   = R & 1;                      // row-half within that t
        const int e0   = g >> 2;
        const int sbase = R2F + tloc * 16384;
        #pragma unroll
        for (int rgl = 0; rgl < 4; rgl++) {
            const int ksp = 4 * Rl + rgl;            // j>>4 within this t
            #pragma unroll
            for (int ntl = 0; ntl < 8; ntl++) {
                const int nt = 8 * C + ntl;
                const int n0 = 64 * C + 8 * ntl + 2 * q;
                const float bb0 = sm[B2O + n0], bb1 = sm[B2O + n0 + 1];
                const int base = sbase + (nt * 8 + ksp) * 128;
                const int s0 = slot_of(2 * q,     g & 3);
                const int s1 = slot_of(2 * q + 1, g & 3);
                sm[base + s0 * 4 + e0    ] = tf32f(acc[rgl][ntl][0] + bb0);  // (j0,n0)
                sm[base + s1 * 4 + e0    ] = tf32f(acc[rgl][ntl][1] + bb1);  // (j0,n1)
                sm[base + s0 * 4 + e0 + 2] = tf32f(acc[rgl][ntl][2] + bb0);  // (j1,n0)
                sm[base + s1 * 4 + e0 + 2] = tf32f(acc[rgl][ntl][3] + bb1);  // (j1,n1)
            }
        }
    }
    __syncthreads();

    // ---------- G3(t0): out_t0 = Main(t0) @ S(t0)  (8 warps, 64x32 tiles) ----------
    zero_acc(acc);
    gemm_frag<8, 4>(&sm[R1F], &sm[R2F], 4 * rg2, 4 * cg, slotl, acc);
    {
        float* op = out + (size_t)t0 * (M_DIM * M_DIM);
        #pragma unroll
        for (int rgl = 0; rgl < 4; rgl++) {
            const int i0 = 64 * rg2 + 16 * rgl + g;
            #pragma unroll
            for (int ntl = 0; ntl < 4; ntl++) {
                const int c0 = 32 * cg + 8 * ntl + 2 * q;
                float2 v0 = make_float2(acc[rgl][ntl][0], acc[rgl][ntl][1]);
                float2 v1 = make_float2(acc[rgl][ntl][2], acc[rgl][ntl][3]);
                *reinterpret_cast<float2*>(op + (size_t)(i0    ) * M_DIM + c0) = v0;
                *reinterpret_cast<float2*>(op + (size_t)(i0 + 8) * M_DIM + c0) = v1;
            }
        }
    }
    __syncthreads();   // Main(t0) reads complete before overwrite

    // ---------- stage Main(t1) -> R1 ----------
    {
        const float* mp = x_main_last + (size_t)(t0 + 1) * (M_DIM * M_DIM);
        #pragma unroll
        for (int it = 0; it < 16; it++) {
            const int idx = tid + it * NTHREADS;
            const int js = idx & 31, ks = (idx >> 5) & 15, rg = idx >> 9;
            int gg, qq; inv_slot(js, gg, qq);
            const int r0 = rg * 16 + gg, c0 = ks * 8 + qq;
            float4 v;
            v.x = tf32f(mp[(r0    ) * M_DIM + c0    ]);
            v.y = tf32f(mp[(r0 + 8) * M_DIM + c0    ]);
            v.z = tf32f(mp[(r0    ) * M_DIM + c0 + 4]);
            v.w = tf32f(mp[(r0 + 8) * M_DIM + c0 + 4]);
            *reinterpret_cast<float4*>(&sm[R1F + idx * 4]) = v;
        }
    }
    __syncthreads();

    // ---------- G3(t1): out_t1 = Main(t1) @ S(t1) ----------
    zero_acc(acc);
    gemm_frag<8, 4>(&sm[R1F], &sm[R2F + 16384], 4 * rg2, 4 * cg, slotl, acc);
    {
        float* op = out + (size_t)(t0 + 1) * (M_DIM * M_DIM);
        #pragma unroll
        for (int rgl = 0; rgl < 4; rgl++) {
            const int i0 = 64 * rg2 + 16 * rgl + g;
            #pragma unroll
            for (int ntl = 0; ntl < 4; ntl++) {
                const int c0 = 32 * cg + 8 * ntl + 2 * q;
                float2 v0 = make_float2(acc[rgl][ntl][0], acc[rgl][ntl][1]);
                float2 v1 = make_float2(acc[rgl][ntl][2], acc[rgl][ntl][3]);
                *reinterpret_cast<float2*>(op + (size_t)(i0    ) * M_DIM + c0) = v0;
                *reinterpret_cast<float2*>(op + (size_t)(i0 + 8) * M_DIM + c0) = v1;
            }
        }
    }
}

extern "C" void kernel_launch(void* const* d_in, const int* in_sizes, int n_in,
                              void* d_out, int out_size) {
    const float* x_main = (const float*)d_in[0];
    const float* x_aux  = (const float*)d_in[1];
    const float* W1     = (const float*)d_in[2];
    const float* b1     = (const float*)d_in[3];
    const float* W2     = (const float*)d_in[4];
    const float* b2     = (const float*)d_in[5];
    float* out = (float*)d_out;

    // last batch of x_main: x_main[N-1, :, 0, :, :]
    const size_t slice = (size_t)T_DIM * M_DIM * M_DIM;
    const float* x_main_last = x_main + ((size_t)in_sizes[0] - slice);

    cudaFuncSetAttribute(slam_dual_kernel,
                         cudaFuncAttributeMaxDynamicSharedMemorySize, SMEM_BYTES);

    pack_weights<<<24, 256>>>(W1, W2);
    slam_dual_kernel<<<T_DIM / 2, NTHREADS, SMEM_BYTES>>>(x_main_last, x_aux, b1, b2, out);
}

// round 13
// speedup vs baseline: 1.1468x; 1.1468x over previous
#include <cuda_runtime.h>
#include <cstdint>
#include <cstddef>

// Problem constants
#define T_DIM 1024
#define M_DIM 128
#define A_DIM 64
#define D_DIM 128
#define NTHREADS 256

// ---------------- packed weight scratch (filled once by pack_weights) ----------------
// B-operand packed layout: entry (nt, ksp, slot) holds float4
//   e0 = B[16*ksp + q    ][8*nt + g]
//   e1 = B[16*ksp + q + 4][8*nt + g]
//   e2 = B[16*ksp + q + 8][8*nt + g]
//   e3 = B[16*ksp + q +12][8*nt + g]
// for consumer lane (g,q) stored at slot = g*4 + ((q + (g>>1)) & 3).
__device__ float g_W1p[16 * 4 * 32 * 4];   // W1: K=64  -> KSP=4   (8192 floats)
__device__ float g_W2p[16 * 8 * 32 * 4];   // W2: K=128 -> KSP=8   (16384 floats)

// ---------------- helpers ----------------
__device__ __forceinline__ unsigned f2tf32(float x) {
    unsigned u;
    asm("cvt.rna.tf32.f32 %0, %1;" : "=r"(u) : "f"(x));
    return u;
}
__device__ __forceinline__ float tf32f(float x) { return __uint_as_float(f2tf32(x)); }
__device__ __forceinline__ float ldcvt(const float* p) { return tf32f(*p); }

__device__ __forceinline__ uint32_t smem_u32(const void* p) {
    uint32_t a;
    asm("{ .reg .u64 t; cvta.to.shared.u64 t, %1; cvt.u32.u64 %0, t; }" : "=r"(a) : "l"(p));
    return a;
}

#define CP_ASYNC16(dst, src) \
    asm volatile("cp.async.cg.shared.global [%0], [%1], 16;" :: "r"(dst), "l"(src) : "memory")
#define CP_COMMIT()  asm volatile("cp.async.commit_group;" ::: "memory")
#define CP_WAIT0()   asm volatile("cp.async.wait_group 0;" ::: "memory")

// lane-slot permutation within a 32-lane packed group (bank spreading)
__device__ __forceinline__ int slot_of(int g, int q) { return g * 4 + ((q + (g >> 1)) & 3); }
__device__ __forceinline__ void inv_slot(int j, int& g, int& q) {
    g = j >> 2;
    q = ((j & 3) + 4 - ((g >> 1) & 3)) & 3;
}

__device__ __forceinline__ void mma_tf32(float c[4],
                                         unsigned a0, unsigned a1, unsigned a2, unsigned a3,
                                         unsigned b0, unsigned b1) {
    asm volatile(
        "mma.sync.aligned.m16n8k8.row.col.f32.tf32.tf32.f32 "
        "{%0,%1,%2,%3}, {%4,%5,%6,%7}, {%8,%9}, {%0,%1,%2,%3};"
        : "+f"(c[0]), "+f"(c[1]), "+f"(c[2]), "+f"(c[3])
        : "r"(a0), "r"(a1), "r"(a2), "r"(a3), "r"(b0), "r"(b1));
}

// ---------------- setup kernel: pack W1/W2 into fragment layout --------------
__global__ void pack_weights(const float* __restrict__ W1, const float* __restrict__ W2) {
    const int idx = blockIdx.x * 256 + threadIdx.x;   // 6144 total
    if (idx < 2048) {                                  // W1p: nt(16) x ksp(4) x slot(32)
        const int js = idx & 31, ksp = (idx >> 5) & 3, nt = idx >> 7;
        int g, q; inv_slot(js, g, q);
        const int n = nt * 8 + g, k0 = ksp * 16 + q;
        float4 v;
        v.x = tf32f(W1[(k0     ) * D_DIM + n]);
        v.y = tf32f(W1[(k0 +  4) * D_DIM + n]);
        v.z = tf32f(W1[(k0 +  8) * D_DIM + n]);
        v.w = tf32f(W1[(k0 + 12) * D_DIM + n]);
        *reinterpret_cast<float4*>(&g_W1p[idx * 4]) = v;
    } else {                                           // W2p: nt(16) x ksp(8) x slot(32)
        const int i2 = idx - 2048;
        const int js = i2 & 31, ksp = (i2 >> 5) & 7, nt = i2 >> 8;
        int g, q; inv_slot(js, g, q);
        const int n = nt * 8 + g, k0 = ksp * 16 + q;
        float4 v;
        v.x = tf32f(W2[(k0     ) * M_DIM + n]);
        v.y = tf32f(W2[(k0 +  4) * M_DIM + n]);
        v.z = tf32f(W2[(k0 +  8) * M_DIM + n]);
        v.w = tf32f(W2[(k0 + 12) * M_DIM + n]);
        *reinterpret_cast<float4*>(&g_W2p[i2 * 4]) = v;
    }
}

// ---------------- pipelined packed-fragment GEMM (64x32 warp tile) ----------------
// A packed: entry (rg, ks, slot) float4 = {A[16rg+g][8ks+q], A[16rg+g+8][8ks+q],
//                                          A[16rg+g][8ks+q+4], A[16rg+g+8][8ks+q+4]}
// B packed: entry (nt, ksp, slot) as documented above. KS = 2*KSP.
// Explicit double-buffer: prefetch ksp+1 operands before issuing ksp's mmas.
template<int KSP>
__device__ __forceinline__ void gemm64(const float* __restrict__ PA,
                                       const float* __restrict__ PB,
                                       int rg2, int cg, int slotl,
                                       float acc[4][4][4]) {
    float4 aE[2][4], aO[2][4], b[2][4];
    #pragma unroll
    for (int rgl = 0; rgl < 4; rgl++) {
        const int rg = 4 * rg2 + rgl;
        aE[0][rgl] = *reinterpret_cast<const float4*>(&PA[((rg * (2 * KSP)    ) * 32 + slotl) * 4]);
        aO[0][rgl] = *reinterpret_cast<const float4*>(&PA[((rg * (2 * KSP) + 1) * 32 + slotl) * 4]);
    }
    #pragma unroll
    for (int ntl = 0; ntl < 4; ntl++)
        b[0][ntl] = *reinterpret_cast<const float4*>(&PB[(((4 * cg + ntl) * KSP) * 32 + slotl) * 4]);

    #pragma unroll
    for (int ksp = 0; ksp < KSP; ksp++) {
        const int cur = ksp & 1, nxt = cur ^ 1;
        if (ksp + 1 < KSP) {
            #pragma unroll
            for (int rgl = 0; rgl < 4; rgl++) {
                const int rg = 4 * rg2 + rgl;
                aE[nxt][rgl] = *reinterpret_cast<const float4*>(
                    &PA[((rg * (2 * KSP) + 2 * (ksp + 1)    ) * 32 + slotl) * 4]);
                aO[nxt][rgl] = *reinterpret_cast<const float4*>(
                    &PA[((rg * (2 * KSP) + 2 * (ksp + 1) + 1) * 32 + slotl) * 4]);
            }
            #pragma unroll
            for (int ntl = 0; ntl < 4; ntl++)
                b[nxt][ntl] = *reinterpret_cast<const float4*>(
                    &PB[(((4 * cg + ntl) * KSP + ksp + 1) * 32 + slotl) * 4]);
        }
        #pragma unroll
        for (int ntl = 0; ntl < 4; ntl++)
            #pragma unroll
            for (int rgl = 0; rgl < 4; rgl++) {
                mma_tf32(acc[rgl][ntl],
                         __float_as_uint(aE[cur][rgl].x), __float_as_uint(aE[cur][rgl].y),
                         __float_as_uint(aE[cur][rgl].z), __float_as_uint(aE[cur][rgl].w),
                         __float_as_uint(b[cur][ntl].x), __float_as_uint(b[cur][ntl].y));
                mma_tf32(acc[rgl][ntl],
                         __float_as_uint(aO[cur][rgl].x), __float_as_uint(aO[cur][rgl].y),
                         __float_as_uint(aO[cur][rgl].z), __float_as_uint(aO[cur][rgl].w),
                         __float_as_uint(b[cur][ntl].z), __float_as_uint(b[cur][ntl].w));
            }
    }
}

// ---------------- pipelined GEMM with row-major raw A (cvt at load) ----------------
// A row-major fp32, row stride LDM=132 floats (bank-conflict-free: lane bank = 4g+q).
// cvt.rna applied per element at load -> numerics identical to pre-converted path.
#define LDM 132
__device__ __forceinline__ void loadA_raw(const float* __restrict__ Ar,
                                          int rg2, int ksp, int g, int q,
                                          float aE[4][4], float aO[4][4]) {
    #pragma unroll
    for (int rgl = 0; rgl < 4; rgl++) {
        const int ra = 64 * rg2 + 16 * rgl + g;
        const float* pa = Ar + ra * LDM + 16 * ksp + q;
        const float* pb = Ar + (ra + 8) * LDM + 16 * ksp + q;
        aE[rgl][0] = ldcvt(pa);      aE[rgl][1] = ldcvt(pb);
        aE[rgl][2] = ldcvt(pa + 4);  aE[rgl][3] = ldcvt(pb + 4);
        aO[rgl][0] = ldcvt(pa + 8);  aO[rgl][1] = ldcvt(pb + 8);
        aO[rgl][2] = ldcvt(pa + 12); aO[rgl][3] = ldcvt(pb + 12);
    }
}

template<int KSP>
__device__ __forceinline__ void gemm64_raw(const float* __restrict__ Ar,
                                           const float* __restrict__ PB,
                                           int rg2, int cg, int g, int q, int slotl,
                                           float acc[4][4][4]) {
    float aE[2][4][4], aO[2][4][4];
    float4 b[2][4];
    loadA_raw(Ar, rg2, 0, g, q, aE[0], aO[0]);
    #pragma unroll
    for (int ntl = 0; ntl < 4; ntl++)
        b[0][ntl] = *reinterpret_cast<const float4*>(&PB[(((4 * cg + ntl) * KSP) * 32 + slotl) * 4]);

    #pragma unroll
    for (int ksp = 0; ksp < KSP; ksp++) {
        const int cur = ksp & 1, nxt = cur ^ 1;
        if (ksp + 1 < KSP) {
            loadA_raw(Ar, rg2, ksp + 1, g, q, aE[nxt], aO[nxt]);
            #pragma unroll
            for (int ntl = 0; ntl < 4; ntl++)
                b[nxt][ntl] = *reinterpret_cast<const float4*>(
                    &PB[(((4 * cg + ntl) * KSP + ksp + 1) * 32 + slotl) * 4]);
        }
        #pragma unroll
        for (int ntl = 0; ntl < 4; ntl++)
            #pragma unroll
            for (int rgl = 0; rgl < 4; rgl++) {
                mma_tf32(acc[rgl][ntl],
                         __float_as_uint(aE[cur][rgl][0]), __float_as_uint(aE[cur][rgl][1]),
                         __float_as_uint(aE[cur][rgl][2]), __float_as_uint(aE[cur][rgl][3]),
                         __float_as_uint(b[cur][ntl].x), __float_as_uint(b[cur][ntl].y));
                mma_tf32(acc[rgl][ntl],
                         __float_as_uint(aO[cur][rgl][0]), __float_as_uint(aO[cur][rgl][1]),
                         __float_as_uint(aO[cur][rgl][2]), __float_as_uint(aO[cur][rgl][3]),
                         __float_as_uint(b[cur][ntl].z), __float_as_uint(b[cur][ntl].w));
            }
    }
}

__device__ __forceinline__ void zero_acc(float acc[4][4][4]) {
    #pragma unroll
    for (int a = 0; a < 4; a++)
        #pragma unroll
        for (int n = 0; n < 4; n++)
            #pragma unroll
            for (int r = 0; r < 4; r++) acc[a][n][r] = 0.0f;
}

// ---------------- SMEM layout (float offsets) ----------------
// R1 [0,16896):      Xp (packed A, 8192 floats)  UNION  Mainr (raw 128 x LDM=132)
// R2 [16896,33280):  Hp (packed A)  UNION  Sp (packed B)
// biases [33280,33536)
#define XPF    0
#define MAINF  0
#define HPF    16896
#define SPF    16896
#define B1O    33280
#define B2O    33408
#define SMEM_FLOATS 33536
#define SMEM_BYTES  (SMEM_FLOATS * 4)   // 134144

__global__ __launch_bounds__(NTHREADS, 1)
void slam_fused_kernel(const float* __restrict__ x_main_last,
                       const float* __restrict__ x_aux,
                       const float* __restrict__ b1,
                       const float* __restrict__ b2,
                       float* __restrict__ out) {
    extern __shared__ float sm[];
    const int t    = blockIdx.x;
    const int tid  = threadIdx.x;
    const int warp = tid >> 5;
    const int lane = tid & 31;
    const int g    = lane >> 2;
    const int q    = lane & 3;
    const int rg2  = warp >> 2;   // 0..1: rows 64*rg2
    const int cg   = warp & 3;    // 0..3: cols 32*cg
    const int slotl = slot_of(g, q);

    // ---------- Phase 0: stage Xp (packed-A gather, rna cvt), biases ----------
    {
        const float* xp = x_aux + (size_t)t * A_DIM;
        #pragma unroll
        for (int it = 0; it < 8; it++) {
            const int idx = tid + it * NTHREADS;            // 2048 entries
            const int js = idx & 31, ks = (idx >> 5) & 7, rg = idx >> 8;
            int gg, qq; inv_slot(js, gg, qq);
            const int r0 = rg * 16 + gg, c0 = ks * 8 + qq;
            const size_t rs = (size_t)(T_DIM * A_DIM);
            float4 v;
            v.x = tf32f(xp[(size_t)(r0    ) * rs + c0    ]);
            v.y = tf32f(xp[(size_t)(r0 + 8) * rs + c0    ]);
            v.z = tf32f(xp[(size_t)(r0    ) * rs + c0 + 4]);
            v.w = tf32f(xp[(size_t)(r0 + 8) * rs + c0 + 4]);
            *reinterpret_cast<float4*>(&sm[XPF + idx * 4]) = v;
        }
        if (tid < 128) {
            sm[B1O + tid] = b1[tid];
            sm[B2O + tid] = b2[tid];
        }
    }
    __syncthreads();

    float acc[4][4][4];
    const int hi  = (q >= 2) ? 2 : 0;
    const int qc0 = (2 * q) & 3;

    // ---------- GEMM1: H = relu(X @ W1 + b1)   (B from global, L1-cached) ----------
    zero_acc(acc);
    gemm64<4>(&sm[XPF], g_W1p, rg2, cg, slotl, acc);
    __syncthreads();   // all GEMM1 reads of R1 done (Main cp.async overwrites below)

    // ---------- issue cp.async Main -> Mainr (raw row-major, overlaps GEMM2) ----------
    {
        const float* mp = x_main_last + (size_t)t * (M_DIM * M_DIM);
        const uint32_t dbase = smem_u32(sm);
        #pragma unroll
        for (int it = 0; it < 16; it++) {
            const int idx = tid + it * NTHREADS;            // 4096 chunks of 16B
            const int row = idx >> 5, ch = idx & 31;
            const uint32_t dst = dbase + (uint32_t)(MAINF + row * LDM + ch * 4) * 4u;
            const float* src = mp + (size_t)row * M_DIM + ch * 4;
            CP_ASYNC16(dst, src);
        }
        CP_COMMIT();
    }

    // epilogue1 -> Hp (packed-A for GEMM2, KS=16)
    #pragma unroll
    for (int rgl = 0; rgl < 4; rgl++) {
        const int rg = 4 * rg2 + rgl;
        #pragma unroll
        for (int ntl = 0; ntl < 4; ntl++) {
            const int ks = 4 * cg + ntl;
            const int d0 = 32 * cg + 8 * ntl + 2 * q;
            const float bb0 = sm[B1O + d0], bb1 = sm[B1O + d0 + 1];
            const int base = HPF + (rg * 16 + ks) * 128;
            const int s0 = slot_of(g, qc0), s1 = slot_of(g, qc0 + 1);
            float2 w0, w1;
            w0.x = tf32f(fmaxf(acc[rgl][ntl][0] + bb0, 0.0f));
            w0.y = tf32f(fmaxf(acc[rgl][ntl][2] + bb0, 0.0f));
            w1.x = tf32f(fmaxf(acc[rgl][ntl][1] + bb1, 0.0f));
            w1.y = tf32f(fmaxf(acc[rgl][ntl][3] + bb1, 0.0f));
            *reinterpret_cast<float2*>(&sm[base + s0 * 4 + hi]) = w0;
            *reinterpret_cast<float2*>(&sm[base + s1 * 4 + hi]) = w1;
        }
    }
    __syncthreads();   // Hp visible

    // ---------- GEMM2: S = H @ W2 + b2   (B from global; Main in flight) ----------
    zero_acc(acc);
    gemm64<8>(&sm[HPF], g_W2p, rg2, cg, slotl, acc);
    __syncthreads();   // all Hp reads done before Sp overwrite

    // epilogue2 -> Sp (packed-B for GEMM3; k-dim = j = GEMM2 output row)
    #pragma unroll
    for (int rgl = 0; rgl < 4; rgl++) {
        const int ksp = 4 * rg2 + rgl;    // j>>4
        const int e0  = g >> 2;
        #pragma unroll
        for (int ntl = 0; ntl < 4; ntl++) {
            const int nt = 4 * cg + ntl;
            const int n0 = 32 * cg + 8 * ntl + 2 * q;
            const float bb0 = sm[B2O + n0], bb1 = sm[B2O + n0 + 1];
            const int base = SPF + (nt * 8 + ksp) * 128;
            const int s0 = slot_of(2 * q,     g & 3);
            const int s1 = slot_of(2 * q + 1, g & 3);
            sm[base + s0 * 4 + e0    ] = tf32f(acc[rgl][ntl][0] + bb0);  // (j0,n0)
            sm[base + s1 * 4 + e0    ] = tf32f(acc[rgl][ntl][1] + bb1);  // (j0,n1)
            sm[base + s0 * 4 + e0 + 2] = tf32f(acc[rgl][ntl][2] + bb0);  // (j1,n0)
            sm[base + s1 * 4 + e0 + 2] = tf32f(acc[rgl][ntl][3] + bb1);  // (j1,n1)
        }
    }
    CP_WAIT0();        // Main chunks arrived (this thread's groups)
    __syncthreads();   // Sp + Mainr visible to all

    // ---------- GEMM3: out_t = Main_t @ S  (A raw + cvt at load, B = Sp) ----------
    zero_acc(acc);
    gemm64_raw<8>(&sm[MAINF], &sm[SPF], rg2, cg, g, q, slotl, acc);

    // epilogue3 -> gmem
    float* op = out + (size_t)t * (M_DIM * M_DIM);
    #pragma unroll
    for (int rgl = 0; rgl < 4; rgl++) {
        const int i0 = 64 * rg2 + 16 * rgl + g;
        #pragma unroll
        for (int ntl = 0; ntl < 4; ntl++) {
            const int c0 = 32 * cg + 8 * ntl + 2 * q;
            float2 v0 = make_float2(acc[rgl][ntl][0], acc[rgl][ntl][1]);
            float2 v1 = make_float2(acc[rgl][ntl][2], acc[rgl][ntl][3]);
            *reinterpret_cast<float2*>(op + (size_t)(i0    ) * M_DIM + c0) = v0;
            *reinterpret_cast<float2*>(op + (size_t)(i0 + 8) * M_DIM + c0) = v1;
        }
    }
}

extern "C" void kernel_launch(void* const* d_in, const int* in_sizes, int n_in,
                              void* d_out, int out_size) {
    const float* x_main = (const float*)d_in[0];
    const float* x_aux  = (const float*)d_in[1];
    const float* W1     = (const float*)d_in[2];
    const float* b1     = (const float*)d_in[3];
    const float* W2     = (const float*)d_in[4];
    const float* b2     = (const float*)d_in[5];
    float* out = (float*)d_out;

    // last batch of x_main: x_main[N-1, :, 0, :, :]
    const size_t slice = (size_t)T_DIM * M_DIM * M_DIM;
    const float* x_main_last = x_main + ((size_t)in_sizes[0] - slice);

    cudaFuncSetAttribute(slam_fused_kernel,
                         cudaFuncAttributeMaxDynamicSharedMemorySize, SMEM_BYTES);

    pack_weights<<<24, 256>>>(W1, W2);
    slam_fused_kernel<<<T_DIM, NTHREADS, SMEM_BYTES>>>(x_main_last, x_aux, b1, b2, out);
}

// round 14
// speedup vs baseline: 1.1475x; 1.0007x over previous
#include <cuda_runtime.h>
#include <cstdint>
#include <cstddef>

// Problem constants
#define T_DIM 1024
#define M_DIM 128
#define A_DIM 64
#define D_DIM 128
#define NTHREADS 256

// ---------------- packed weight scratch (filled once by pack_weights) ----------------
// B-operand packed layout: entry (nt, ksp, slot) holds float4
//   e0 = B[16*ksp + q    ][8*nt + g]
//   e1 = B[16*ksp + q + 4][8*nt + g]
//   e2 = B[16*ksp + q + 8][8*nt + g]
//   e3 = B[16*ksp + q +12][8*nt + g]
// for consumer lane (g,q) stored at slot = g*4 + ((q + (g>>1)) & 3).
__device__ float g_W1p[16 * 4 * 32 * 4];   // W1: K=64  -> KSP=4   (8192 floats)
__device__ float g_W2p[16 * 8 * 32 * 4];   // W2: K=128 -> KSP=8   (16384 floats)

// ---------------- helpers ----------------
__device__ __forceinline__ unsigned f2tf32(float x) {
    unsigned u;
    asm("cvt.rna.tf32.f32 %0, %1;" : "=r"(u) : "f"(x));
    return u;
}
__device__ __forceinline__ float tf32f(float x) { return __uint_as_float(f2tf32(x)); }
__device__ __forceinline__ float ldcvt(const float* p) { return tf32f(*p); }

__device__ __forceinline__ uint32_t smem_u32(const void* p) {
    uint32_t a;
    asm("{ .reg .u64 t; cvta.to.shared.u64 t, %1; cvt.u32.u64 %0, t; }" : "=r"(a) : "l"(p));
    return a;
}

#define CP_ASYNC16(dst, src) \
    asm volatile("cp.async.cg.shared.global [%0], [%1], 16;" :: "r"(dst), "l"(src) : "memory")
#define CP_COMMIT()  asm volatile("cp.async.commit_group;" ::: "memory")
#define CP_WAIT0()   asm volatile("cp.async.wait_group 0;" ::: "memory")

// lane-slot permutation within a 32-lane packed group (bank spreading)
__device__ __forceinline__ int slot_of(int g, int q) { return g * 4 + ((q + (g >> 1)) & 3); }
__device__ __forceinline__ void inv_slot(int j, int& g, int& q) {
    g = j >> 2;
    q = ((j & 3) + 4 - ((g >> 1) & 3)) & 3;
}

__device__ __forceinline__ void mma_tf32(float c[4],
                                         unsigned a0, unsigned a1, unsigned a2, unsigned a3,
                                         unsigned b0, unsigned b1) {
    asm volatile(
        "mma.sync.aligned.m16n8k8.row.col.f32.tf32.tf32.f32 "
        "{%0,%1,%2,%3}, {%4,%5,%6,%7}, {%8,%9}, {%0,%1,%2,%3};"
        : "+f"(c[0]), "+f"(c[1]), "+f"(c[2]), "+f"(c[3])
        : "r"(a0), "r"(a1), "r"(a2), "r"(a3), "r"(b0), "r"(b1));
}

// ---------------- setup kernel: pack W1/W2 into fragment layout --------------
__global__ void pack_weights(const float* __restrict__ W1, const float* __restrict__ W2) {
    const int idx = blockIdx.x * 256 + threadIdx.x;   // 6144 total
    if (idx < 2048) {                                  // W1p: nt(16) x ksp(4) x slot(32)
        const int js = idx & 31, ksp = (idx >> 5) & 3, nt = idx >> 7;
        int g, q; inv_slot(js, g, q);
        const int n = nt * 8 + g, k0 = ksp * 16 + q;
        float4 v;
        v.x = tf32f(W1[(k0     ) * D_DIM + n]);
        v.y = tf32f(W1[(k0 +  4) * D_DIM + n]);
        v.z = tf32f(W1[(k0 +  8) * D_DIM + n]);
        v.w = tf32f(W1[(k0 + 12) * D_DIM + n]);
        *reinterpret_cast<float4*>(&g_W1p[idx * 4]) = v;
    } else {                                           // W2p: nt(16) x ksp(8) x slot(32)
        const int i2 = idx - 2048;
        const int js = i2 & 31, ksp = (i2 >> 5) & 7, nt = i2 >> 8;
        int g, q; inv_slot(js, g, q);
        const int n = nt * 8 + g, k0 = ksp * 16 + q;
        float4 v;
        v.x = tf32f(W2[(k0     ) * M_DIM + n]);
        v.y = tf32f(W2[(k0 +  4) * M_DIM + n]);
        v.z = tf32f(W2[(k0 +  8) * M_DIM + n]);
        v.w = tf32f(W2[(k0 + 12) * M_DIM + n]);
        *reinterpret_cast<float4*>(&g_W2p[i2 * 4]) = v;
    }
}

// ---------------- pipelined packed-fragment GEMM (64x32 warp tile) ----------------
// A packed: entry (rg, ks, slot) float4; B packed: entry (nt, ksp, slot). KS = 2*KSP.
// Explicit double-buffer: prefetch ksp+1 operands before issuing ksp's mmas.
template<int KSP>
__device__ __forceinline__ void gemm64(const float* __restrict__ PA,
                                       const float* __restrict__ PB,
                                       int rg2, int cg, int slotl,
                                       float acc[4][4][4]) {
    float4 aE[2][4], aO[2][4], b[2][4];
    #pragma unroll
    for (int rgl = 0; rgl < 4; rgl++) {
        const int rg = 4 * rg2 + rgl;
        aE[0][rgl] = *reinterpret_cast<const float4*>(&PA[((rg * (2 * KSP)    ) * 32 + slotl) * 4]);
        aO[0][rgl] = *reinterpret_cast<const float4*>(&PA[((rg * (2 * KSP) + 1) * 32 + slotl) * 4]);
    }
    #pragma unroll
    for (int ntl = 0; ntl < 4; ntl++)
        b[0][ntl] = *reinterpret_cast<const float4*>(&PB[(((4 * cg + ntl) * KSP) * 32 + slotl) * 4]);

    #pragma unroll
    for (int ksp = 0; ksp < KSP; ksp++) {
        const int cur = ksp & 1, nxt = cur ^ 1;
        if (ksp + 1 < KSP) {
            #pragma unroll
            for (int rgl = 0; rgl < 4; rgl++) {
                const int rg = 4 * rg2 + rgl;
                aE[nxt][rgl] = *reinterpret_cast<const float4*>(
                    &PA[((rg * (2 * KSP) + 2 * (ksp + 1)    ) * 32 + slotl) * 4]);
                aO[nxt][rgl] = *reinterpret_cast<const float4*>(
                    &PA[((rg * (2 * KSP) + 2 * (ksp + 1) + 1) * 32 + slotl) * 4]);
            }
            #pragma unroll
            for (int ntl = 0; ntl < 4; ntl++)
                b[nxt][ntl] = *reinterpret_cast<const float4*>(
                    &PB[(((4 * cg + ntl) * KSP + ksp + 1) * 32 + slotl) * 4]);
        }
        #pragma unroll
        for (int ntl = 0; ntl < 4; ntl++)
            #pragma unroll
            for (int rgl = 0; rgl < 4; rgl++) {
                mma_tf32(acc[rgl][ntl],
                         __float_as_uint(aE[cur][rgl].x), __float_as_uint(aE[cur][rgl].y),
                         __float_as_uint(aE[cur][rgl].z), __float_as_uint(aE[cur][rgl].w),
                         __float_as_uint(b[cur][ntl].x), __float_as_uint(b[cur][ntl].y));
                mma_tf32(acc[rgl][ntl],
                         __float_as_uint(aO[cur][rgl].x), __float_as_uint(aO[cur][rgl].y),
                         __float_as_uint(aO[cur][rgl].z), __float_as_uint(aO[cur][rgl].w),
                         __float_as_uint(b[cur][ntl].z), __float_as_uint(b[cur][ntl].w));
            }
    }
}

// ---------------- pipelined GEMM with row-major raw A (cvt at load) ----------------
// A row-major fp32 in smem, row stride LDA floats (LDA % 32 == 4 -> lane bank = 4g+q,
// all 32 lanes distinct -> conflict-free). cvt.rna applied at load (numerics identical
// to pre-converted path).
template<int LDA>
__device__ __forceinline__ void loadA_raw(const float* __restrict__ Ar,
                                          int rg2, int ksp, int g, int q,
                                          float aE[4][4], float aO[4][4]) {
    #pragma unroll
    for (int rgl = 0; rgl < 4; rgl++) {
        const int ra = 64 * rg2 + 16 * rgl + g;
        const float* pa = Ar + ra * LDA + 16 * ksp + q;
        const float* pb = Ar + (ra + 8) * LDA + 16 * ksp + q;
        aE[rgl][0] = ldcvt(pa);      aE[rgl][1] = ldcvt(pb);
        aE[rgl][2] = ldcvt(pa + 4);  aE[rgl][3] = ldcvt(pb + 4);
        aO[rgl][0] = ldcvt(pa + 8);  aO[rgl][1] = ldcvt(pb + 8);
        aO[rgl][2] = ldcvt(pa + 12); aO[rgl][3] = ldcvt(pb + 12);
    }
}

template<int KSP, int LDA>
__device__ __forceinline__ void gemm64_raw(const float* __restrict__ Ar,
                                           const float* __restrict__ PB,
                                           int rg2, int cg, int g, int q, int slotl,
                                           float acc[4][4][4]) {
    float aE[2][4][4], aO[2][4][4];
    float4 b[2][4];
    loadA_raw<LDA>(Ar, rg2, 0, g, q, aE[0], aO[0]);
    #pragma unroll
    for (int ntl = 0; ntl < 4; ntl++)
        b[0][ntl] = *reinterpret_cast<const float4*>(&PB[(((4 * cg + ntl) * KSP) * 32 + slotl) * 4]);

    #pragma unroll
    for (int ksp = 0; ksp < KSP; ksp++) {
        const int cur = ksp & 1, nxt = cur ^ 1;
        if (ksp + 1 < KSP) {
            loadA_raw<LDA>(Ar, rg2, ksp + 1, g, q, aE[nxt], aO[nxt]);
            #pragma unroll
            for (int ntl = 0; ntl < 4; ntl++)
                b[nxt][ntl] = *reinterpret_cast<const float4*>(
                    &PB[(((4 * cg + ntl) * KSP + ksp + 1) * 32 + slotl) * 4]);
        }
        #pragma unroll
        for (int ntl = 0; ntl < 4; ntl++)
            #pragma unroll
            for (int rgl = 0; rgl < 4; rgl++) {
                mma_tf32(acc[rgl][ntl],
                         __float_as_uint(aE[cur][rgl][0]), __float_as_uint(aE[cur][rgl][1]),
                         __float_as_uint(aE[cur][rgl][2]), __float_as_uint(aE[cur][rgl][3]),
                         __float_as_uint(b[cur][ntl].x), __float_as_uint(b[cur][ntl].y));
                mma_tf32(acc[rgl][ntl],
                         __float_as_uint(aO[cur][rgl][0]), __float_as_uint(aO[cur][rgl][1]),
                         __float_as_uint(aO[cur][rgl][2]), __float_as_uint(aO[cur][rgl][3]),
                         __float_as_uint(b[cur][ntl].z), __float_as_uint(b[cur][ntl].w));
            }
    }
}

__device__ __forceinline__ void zero_acc(float acc[4][4][4]) {
    #pragma unroll
    for (int a = 0; a < 4; a++)
        #pragma unroll
        for (int n = 0; n < 4; n++)
            #pragma unroll
            for (int r = 0; r < 4; r++) acc[a][n][r] = 0.0f;
}

// ---------------- SMEM layout (float offsets) ----------------
// Xraw ping-pong: 2 x (128 rows x LDX=68)        [0, 17408)
// Mainr: raw 128 x LDM=132                       [17408, 34304)
// Hp UNION Sp (packed, 16384)                    [34304, 50688)
// biases                                         [50688, 50944)
#define LDX    68
#define LDM    132
#define XB0    0
#define XB1    8704
#define MAINF  17408
#define HPF    34304
#define SPF    34304
#define B1O    50688
#define B2O    50816
#define SMEM_FLOATS 50944
#define SMEM_BYTES  (SMEM_FLOATS * 4)   // 203776

__global__ __launch_bounds__(NTHREADS, 1)
void slam_persist_kernel(const float* __restrict__ x_main_last,
                         const float* __restrict__ x_aux,
                         const float* __restrict__ b1,
                         const float* __restrict__ b2,
                         float* __restrict__ out) {
    extern __shared__ float sm[];
    const int tid  = threadIdx.x;
    const int warp = tid >> 5;
    const int lane = tid & 31;
    const int g    = lane >> 2;
    const int q    = lane & 3;
    const int rg2  = warp >> 2;   // 0..1: rows 64*rg2
    const int cg   = warp & 3;    // 0..3: cols 32*cg
    const int slotl  = slot_of(g, q);
    const int stride = gridDim.x;
    const uint32_t dbase = smem_u32(sm);

    // ---- cp.async issue helpers (per-thread chunk sets) ----
    // X(t) -> xbuf: 2048 16B chunks (8/thread): row m = idx>>4, ch = idx&15
    auto issue_x = [&](int t, int xoff) {
        const float* xp = x_aux + (size_t)t * A_DIM;
        #pragma unroll
        for (int it = 0; it < 8; it++) {
            const int idx = tid + it * NTHREADS;
            const int m = idx >> 4, ch = idx & 15;
            const uint32_t dst = dbase + (uint32_t)(xoff + m * LDX + ch * 4) * 4u;
            const float* src = xp + (size_t)m * (T_DIM * A_DIM) + ch * 4;
            CP_ASYNC16(dst, src);
        }
    };
    // Main(t) -> Mainr: 4096 16B chunks (16/thread)
    auto issue_main = [&](int t) {
        const float* mp = x_main_last + (size_t)t * (M_DIM * M_DIM);
        #pragma unroll
        for (int it = 0; it < 16; it++) {
            const int idx = tid + it * NTHREADS;
            const int row = idx >> 5, ch = idx & 31;
            const uint32_t dst = dbase + (uint32_t)(MAINF + row * LDM + ch * 4) * 4u;
            const float* src = mp + (size_t)row * M_DIM + ch * 4;
            CP_ASYNC16(dst, src);
        }
    };

    // ---------- prologue: biases + X(t0) ----------
    if (tid < 128) {
        sm[B1O + tid] = b1[tid];
        sm[B2O + tid] = b2[tid];
    }
    const int t0 = blockIdx.x;
    if (t0 < T_DIM) {
        issue_x(t0, XB0);
        CP_COMMIT();
        CP_WAIT0();
    }
    __syncthreads();

    float acc[4][4][4];
    const int hi  = (q >= 2) ? 2 : 0;
    const int qc0 = (2 * q) & 3;

    int p = 0;
    for (int t = t0; t < T_DIM; t += stride) {
        // ---------- issue prefetches: Main(t), X(t+stride) ----------
        issue_main(t);
        const int tn = t + stride;
        if (tn < T_DIM) issue_x(tn, p ? XB0 : XB1);
        CP_COMMIT();

        // ---------- GEMM1: H = relu(X @ W1 + b1)  (raw X, cvt at load) ----------
        zero_acc(acc);
        gemm64_raw<4, LDX>(&sm[p ? XB1 : XB0], g_W1p, rg2, cg, g, q, slotl, acc);

        // epilogue1 -> Hp (packed-A for GEMM2, KS=16)
        #pragma unroll
        for (int rgl = 0; rgl < 4; rgl++) {
            const int rg = 4 * rg2 + rgl;
            #pragma unroll
            for (int ntl = 0; ntl < 4; ntl++) {
                const int ks = 4 * cg + ntl;
                const int d0 = 32 * cg + 8 * ntl + 2 * q;
                const float bb0 = sm[B1O + d0], bb1 = sm[B1O + d0 + 1];
                const int base = HPF + (rg * 16 + ks) * 128;
                const int s0 = slot_of(g, qc0), s1 = slot_of(g, qc0 + 1);
                float2 w0, w1;
                w0.x = tf32f(fmaxf(acc[rgl][ntl][0] + bb0, 0.0f));
                w0.y = tf32f(fmaxf(acc[rgl][ntl][2] + bb0, 0.0f));
                w1.x = tf32f(fmaxf(acc[rgl][ntl][1] + bb1, 0.0f));
                w1.y = tf32f(fmaxf(acc[rgl][ntl][3] + bb1, 0.0f));
                *reinterpret_cast<float2*>(&sm[base + s0 * 4 + hi]) = w0;
                *reinterpret_cast<float2*>(&sm[base + s1 * 4 + hi]) = w1;
            }
        }
        __syncthreads();   // B1: Hp visible

        // ---------- GEMM2: S = H @ W2 + b2  (B from global; prefetches in flight) ----------
        zero_acc(acc);
        gemm64<8>(&sm[HPF], g_W2p, rg2, cg, slotl, acc);
        __syncthreads();   // B2: Hp reads done (Sp overwrites same region)

        // epilogue2 -> Sp (packed-B for GEMM3; k-dim = j = GEMM2 output row)
        #pragma unroll
        for (int rgl = 0; rgl < 4; rgl++) {
            const int ksp = 4 * rg2 + rgl;    // j>>4
            const int e0  = g >> 2;
            #pragma unroll
            for (int ntl = 0; ntl < 4; ntl++) {
                const int nt = 4 * cg + ntl;
                const int n0 = 32 * cg + 8 * ntl + 2 * q;
                const float bb0 = sm[B2O + n0], bb1 = sm[B2O + n0 + 1];
                const int base = SPF + (nt * 8 + ksp) * 128;
                const int s0 = slot_of(2 * q,     g & 3);
                const int s1 = slot_of(2 * q + 1, g & 3);
                sm[base + s0 * 4 + e0    ] = tf32f(acc[rgl][ntl][0] + bb0);  // (j0,n0)
                sm[base + s1 * 4 + e0    ] = tf32f(acc[rgl][ntl][1] + bb1);  // (j0,n1)
                sm[base + s0 * 4 + e0 + 2] = tf32f(acc[rgl][ntl][2] + bb0);  // (j1,n0)
                sm[base + s1 * 4 + e0 + 2] = tf32f(acc[rgl][ntl][3] + bb1);  // (j1,n1)
            }
        }
        CP_WAIT0();        // Main(t) + X(t+stride) arrived (this thread's chunks)
        __syncthreads();   // B3: Sp + Mainr (+ next X) visible to all

        // ---------- GEMM3: out_t = Main_t @ S  (raw Main + cvt at load) ----------
        zero_acc(acc);
        gemm64_raw<8, LDM>(&sm[MAINF], &sm[SPF], rg2, cg, g, q, slotl, acc);
        __syncthreads();   // B4: Mainr + Sp reads done (next iter may overwrite)

        // epilogue3 -> gmem (overlaps next iteration's prefetch + GEMM1)
        float* op = out + (size_t)t * (M_DIM * M_DIM);
        #pragma unroll
        for (int rgl = 0; rgl < 4; rgl++) {
            const int i0 = 64 * rg2 + 16 * rgl + g;
            #pragma unroll
            for (int ntl = 0; ntl < 4; ntl++) {
                const int c0 = 32 * cg + 8 * ntl + 2 * q;
                float2 v0 = make_float2(acc[rgl][ntl][0], acc[rgl][ntl][1]);
                float2 v1 = make_float2(acc[rgl][ntl][2], acc[rgl][ntl][3]);
                *reinterpret_cast<float2*>(op + (size_t)(i0    ) * M_DIM + c0) = v0;
                *reinterpret_cast<float2*>(op + (size_t)(i0 + 8) * M_DIM + c0) = v1;
            }
        }
        p ^= 1;
    }
}

extern "C" void kernel_launch(void* const* d_in, const int* in_sizes, int n_in,
                              void* d_out, int out_size) {
    const float* x_main = (const float*)d_in[0];
    const float* x_aux  = (const float*)d_in[1];
    const float* W1     = (const float*)d_in[2];
    const float* b1     = (const float*)d_in[3];
    const float* W2     = (const float*)d_in[4];
    const float* b2     = (const float*)d_in[5];
    float* out = (float*)d_out;

    // last batch of x_main: x_main[N-1, :, 0, :, :]
    const size_t slice = (size_t)T_DIM * M_DIM * M_DIM;
    const float* x_main_last = x_main + ((size_t)in_sizes[0] - slice);

    int nsm = 148;
    cudaDeviceGetAttribute(&nsm, cudaDevAttrMultiProcessorCount, 0);
    if (nsm < 1 || nsm > T_DIM) nsm = 148;

    cudaFuncSetAttribute(slam_persist_kernel,
                         cudaFuncAttributeMaxDynamicSharedMemorySize, SMEM_BYTES);

    pack_weights<<<24, 256>>>(W1, W2);
    slam_persist_kernel<<<nsm, NTHREADS, SMEM_BYTES>>>(x_main_last, x_aux, b1, b2, out);
}